// round 5
// baseline (speedup 1.0000x reference)
#include <cuda_runtime.h>
#include <math.h>

// InteractingLayer (AutoInt): B=4096, F=50, E=64, H=4, D=32.
// v2: 256 threads, smem 109KB -> 2 CTAs/SM. Softmax fused in registers.
// R-projection fused into epilogue. f32x2 everywhere.

#define BB 4096
#define FF 50
#define EE 64
#define CC 128

#define XS_OFF 0            // Xs[50][64]            3200
#define Q_OFF  3200         // Q [50][132]           6600
#define KT_OFF 9800         // Kt[128][53]           6784
#define VB_OFF 16584        // Vb[50][132] (K tmp -> V) 6600
#define WS_OFF 23184        // Ws[32][128]           4096
#define SMEM_FLOATS 27280
#define SMEM_BYTES (SMEM_FLOATS * 4)   // 109120

#define S_OFF 3200          // A[4*50][52] aliases Q+Kt (3200..13600 < 16584)
#define S_STRIDE 52
#define KT_STRIDE 53
#define PB_STRIDE 132

typedef unsigned long long ull;

__device__ __forceinline__ ull pack2(float lo, float hi) {
    ull r; asm("mov.b64 %0,{%1,%2};" : "=l"(r) : "f"(lo), "f"(hi)); return r;
}
__device__ __forceinline__ void unpack2(ull v, float& lo, float& hi) {
    asm("mov.b64 {%0,%1},%2;" : "=f"(lo), "=f"(hi) : "l"(v));
}
__device__ __forceinline__ void ffma2(ull& d, ull a, ull b) {
    asm("fma.rn.f32x2 %0,%1,%2,%3;" : "=l"(d) : "l"(a), "l"(b), "l"(d));
}

__global__ void __launch_bounds__(256, 2)
autoint_v2(const float* __restrict__ X,
           const float* __restrict__ Wq, const float* __restrict__ Wk,
           const float* __restrict__ Wv, const float* __restrict__ Wr,
           float* __restrict__ out)
{
    extern __shared__ float sm[];
    float* Xs = sm + XS_OFF;
    float* Qb = sm + Q_OFF;
    float* Kt = sm + KT_OFF;
    float* Vb = sm + VB_OFF;
    float* Ws = sm + WS_OFF;
    float* Sb = sm + S_OFF;

    const int tid  = threadIdx.x;
    const int b    = blockIdx.x;
    const int lane = tid & 31;
    const int warp = tid >> 5;

    const float* Xb = X + (size_t)b * (FF * EE);

    // ---- Load X [50][64] (row-major, broadcast-read later)
    {
        const float4* src = (const float4*)Xb;
        float4* dst = (float4*)Xs;
        for (int i = tid; i < 800; i += 256) dst[i] = src[i];
    }

    // ---- Projections Q, K(->Kt via Vb temp), V.
    // Thread tile: 8 rows (4ty..4ty+3, 32+4ty..35+4ty) x 4 cols (4tx..4tx+3).
    const int tx = tid & 31;
    const int ty = tid >> 5;

    for (int m = 0; m < 3; ++m) {
        const float* Wsrc = (m == 0) ? Wq : ((m == 1) ? Wk : Wv);
        float* dst = (m == 0) ? Qb : Vb;

        ull acc[8][2];
        #pragma unroll
        for (int r = 0; r < 8; ++r) { acc[r][0] = 0ull; acc[r][1] = 0ull; }

        for (int h2 = 0; h2 < 2; ++h2) {
            __syncthreads();
            {   // stage 32x128 half of W (16KB)
                const float4* s4 = (const float4*)(Wsrc + h2 * 4096);
                float4* d4 = (float4*)Ws;
                #pragma unroll
                for (int i = 0; i < 4; ++i) d4[tid + 256 * i] = s4[tid + 256 * i];
            }
            __syncthreads();

            #pragma unroll 4
            for (int e = 0; e < 32; ++e) {
                float4 wv = *(const float4*)(Ws + e * CC + 4 * tx);  // conflict-free
                ull w01 = pack2(wv.x, wv.y);
                ull w23 = pack2(wv.z, wv.w);
                const int eg = h2 * 32 + e;
                #pragma unroll
                for (int r = 0; r < 8; ++r) {
                    int f = (r < 4) ? (4 * ty + r) : (28 + 4 * ty + r);  // 0..63
                    float x = Xs[f * EE + eg];   // broadcast; rows>=50 garbage, discarded
                    ull xx = pack2(x, x);
                    ffma2(acc[r][0], xx, w01);
                    ffma2(acc[r][1], xx, w23);
                }
            }
        }
        #pragma unroll
        for (int r = 0; r < 8; ++r) {
            int f = (r < 4) ? (4 * ty + r) : (28 + 4 * ty + r);
            if (f < FF) {
                float4 o;
                unpack2(acc[r][0], o.x, o.y);
                unpack2(acc[r][1], o.z, o.w);
                *(float4*)(dst + f * PB_STRIDE + 4 * tx) = o;
            }
        }

        if (m == 1) {
            __syncthreads();
            // transpose K: Vb[g][c] -> Kt[c][g]  (stride 53 => conflict-free writes)
            for (int i = tid; i < FF * CC; i += 256) {
                int g = i >> 7, c = i & 127;
                Kt[c * KT_STRIDE + g] = Vb[g * PB_STRIDE + c];
            }
            // next loop iteration starts with __syncthreads (covers WAR on Vb)
        }
    }
    __syncthreads();

    // ---- Scores + softmax, fully in registers.
    // 16 tasks: h = t>>2, row group f0 = 13*(t&3), 13 rows (last group 11).
    // Warp w does t = w and t = w+8. Results held packed until block-wide sync.
    {
        ull acc[2][13];
        #pragma unroll
        for (int s = 0; s < 2; ++s) {
            const int t   = warp + 8 * s;
            const int h   = t >> 2;
            const int grp = t & 3;
            const int f0  = 13 * grp;
            const int c0  = 32 * h;

            int qoff[13];
            #pragma unroll
            for (int r = 0; r < 13; ++r) {
                int f = f0 + r; if (f > 49) f = 49;       // clamp (dups discarded)
                qoff[r] = f * PB_STRIDE;
            }
            #pragma unroll
            for (int r = 0; r < 13; ++r) acc[s][r] = 0ull;

            const float* Qh   = Qb + c0;
            const float* kcol = Kt + c0 * KT_STRIDE + lane;
            #pragma unroll 2
            for (int d = 0; d < 32; ++d) {
                ull kk = pack2(kcol[d * KT_STRIDE], kcol[d * KT_STRIDE + 32]);
                #pragma unroll
                for (int r = 0; r < 13; ++r) {
                    float q = Qh[qoff[r] + d];            // broadcast
                    ffma2(acc[s][r], pack2(q, q), kk);
                }
            }
            // in-register softmax: row = (lo half: g=lane, hi half: g=lane+32)
            #pragma unroll
            for (int r = 0; r < 13; ++r) {
                float v0, v1; unpack2(acc[s][r], v0, v1);
                if (lane >= FF - 32) v1 = -3.4e38f;
                float mx = fmaxf(v0, v1);
                #pragma unroll
                for (int o = 16; o; o >>= 1) mx = fmaxf(mx, __shfl_xor_sync(0xffffffffu, mx, o));
                float e0 = __expf(v0 - mx);
                float e1 = (lane < FF - 32) ? __expf(v1 - mx) : 0.f;
                float su = e0 + e1;
                #pragma unroll
                for (int o = 16; o; o >>= 1) su += __shfl_xor_sync(0xffffffffu, su, o);
                float inv = 1.0f / su;
                acc[s][r] = pack2(e0 * inv, e1 * inv);
            }
        }

        __syncthreads();   // all Q/Kt reads done before S overwrites that region

        #pragma unroll
        for (int s = 0; s < 2; ++s) {
            const int t   = warp + 8 * s;
            const int h   = t >> 2;
            const int grp = t & 3;
            const int f0  = 13 * grp;
            const int nr  = (grp == 3) ? 11 : 13;
            #pragma unroll
            for (int r = 0; r < 13; ++r) {
                if (r < nr) {
                    float a0, a1; unpack2(acc[s][r], a0, a1);
                    float* row = Sb + (h * FF + f0 + r) * S_STRIDE;
                    row[lane] = a0;
                    if (lane < FF - 32) row[32 + lane] = a1;
                }
            }
        }
    }
    __syncthreads();

    // ---- AV + R(=X@Wr) + ReLU. Thread owns col jj, rows f = fb, fb+2, ... (25 rows).
    // f32x2 packs (g,g+1) for AV and (e,e+1) for R; horizontal add at the end.
    {
        const int jj = tid & 127;
        const int fb = tid >> 7;            // 0..1
        const int h  = jj >> 5;
        const float* Sh = Sb + h * FF * S_STRIDE;

        ull acc[25];
        #pragma unroll
        for (int i = 0; i < 25; ++i) acc[i] = 0ull;

        #pragma unroll 2
        for (int g2 = 0; g2 < 25; ++g2) {
            const int g = 2 * g2;
            ull vv = pack2(Vb[g * PB_STRIDE + jj], Vb[(g + 1) * PB_STRIDE + jj]);
            #pragma unroll
            for (int i = 0; i < 25; ++i) {
                const int f = fb + 2 * i;
                ull aa = *(const ull*)(Sh + f * S_STRIDE + g);   // LDS.64 broadcast
                ffma2(acc[i], aa, vv);
            }
        }

        for (int h2 = 0; h2 < 2; ++h2) {
            __syncthreads();
            {   // stage Wr half
                const float4* s4 = (const float4*)(Wr + h2 * 4096);
                float4* d4 = (float4*)Ws;
                #pragma unroll
                for (int i2 = 0; i2 < 4; ++i2) d4[tid + 256 * i2] = s4[tid + 256 * i2];
            }
            __syncthreads();

            #pragma unroll 2
            for (int e2 = 0; e2 < 16; ++e2) {
                const int e = 2 * e2;
                ull ww = pack2(Ws[e * CC + jj], Ws[(e + 1) * CC + jj]);
                const int eg = h2 * 32 + e;
                #pragma unroll
                for (int i = 0; i < 25; ++i) {
                    const int f = fb + 2 * i;
                    ull xx = *(const ull*)(Xs + f * EE + eg);    // LDS.64 broadcast
                    ffma2(acc[i], xx, ww);
                }
            }
        }

        float* outB = out + (size_t)b * (FF * CC);
        #pragma unroll
        for (int i = 0; i < 25; ++i) {
            const int f = fb + 2 * i;
            float lo, hi; unpack2(acc[i], lo, hi);
            outB[f * CC + jj] = fmaxf(lo + hi, 0.f);     // coalesced
        }
    }
}

extern "C" void kernel_launch(void* const* d_in, const int* in_sizes, int n_in,
                              void* d_out, int out_size)
{
    const float* X  = (const float*)d_in[0];
    const float* Wq = (const float*)d_in[1];
    const float* Wk = (const float*)d_in[2];
    const float* Wv = (const float*)d_in[3];
    const float* Wr = (const float*)d_in[4];
    float* out = (float*)d_out;

    cudaFuncSetAttribute(autoint_v2,
                         cudaFuncAttributeMaxDynamicSharedMemorySize, SMEM_BYTES);
    autoint_v2<<<BB, 256, SMEM_BYTES>>>(X, Wq, Wk, Wv, Wr, out);
}

// round 7
// speedup vs baseline: 1.5135x; 1.5135x over previous
#include <cuda_runtime.h>
#include <math.h>

// InteractingLayer (AutoInt): B=4096, F=50, E=64, H=4, D=32.
// v3: all smem broadcasts vectorized to 128b; pair-interleaved K layout so
// scores need no per-row repacks; 24-task score split; 2 CTAs/SM (107KB smem).

#define BB 4096
#define FF 50
#define EE 64
#define CC 128

#define XS_OFF  0            // Xs [50][64]                    3200
#define Q_OFF   3200         // Qb [50][128]                   6400
#define KTP_OFF 9600         // Ktp[64][104] pair-interleaved  6656
#define VB_OFF  16256        // Vb [50][128] (K tmp -> V)      6400
#define WS_OFF  22656        // Ws [32][128] staging           4096
#define SMEM_FLOATS 26752
#define SMEM_BYTES (SMEM_FLOATS * 4)     // 107008 -> 2 CTAs/SM

#define S_OFF 3200           // Sb[4*50][52] aliases Qb+Ktp (3200..13600 < 16256)
#define S_STRIDE 52
#define KTP_STRIDE 104

typedef unsigned long long ull;

__device__ __forceinline__ ull pack2(float lo, float hi) {
    ull r; asm("mov.b64 %0,{%1,%2};" : "=l"(r) : "f"(lo), "f"(hi)); return r;
}
__device__ __forceinline__ void unpack2(ull v, float& lo, float& hi) {
    asm("mov.b64 {%0,%1},%2;" : "=f"(lo), "=f"(hi) : "l"(v));
}
__device__ __forceinline__ void ffma2(ull& d, ull a, ull b) {
    asm("fma.rn.f32x2 %0,%1,%2,%3;" : "=l"(d) : "l"(a), "l"(b), "l"(d));
}

__global__ void __launch_bounds__(256, 2)
autoint_v3(const float* __restrict__ X,
           const float* __restrict__ Wq, const float* __restrict__ Wk,
           const float* __restrict__ Wv, const float* __restrict__ Wr,
           float* __restrict__ out)
{
    extern __shared__ float sm[];
    float* Xs  = sm + XS_OFF;
    float* Qb  = sm + Q_OFF;
    float* Ktp = sm + KTP_OFF;
    float* Vb  = sm + VB_OFF;
    float* Ws  = sm + WS_OFF;
    float* Sb  = sm + S_OFF;

    const int tid  = threadIdx.x;
    const int b    = blockIdx.x;
    const int lane = tid & 31;
    const int warp = tid >> 5;
    const int tx   = tid & 31;
    const int ty   = tid >> 5;

    const float* Xb = X + (size_t)b * (FF * EE);

    // ---- Load X [50][64] row-major
    {
        const float4* src = (const float4*)Xb;
        float4* dst = (float4*)Xs;
        for (int i = tid; i < 800; i += 256) dst[i] = src[i];
    }

    // Precomputed (clamped) row indices for the 8-row projection tile
    int frow[8], xoff[8];
    #pragma unroll
    for (int r = 0; r < 8; ++r) {
        int f = (r < 4) ? (4 * ty + r) : (28 + 4 * ty + r);   // 0..59
        frow[r] = f;
        xoff[r] = ((f < FF) ? f : (FF - 1)) * EE;
    }

    // ---- Projections Q, K(->Ktp), V. float4 X broadcasts; f32x2 FMA.
    for (int m = 0; m < 3; ++m) {
        const float* Wsrc = (m == 0) ? Wq : ((m == 1) ? Wk : Wv);
        float* dst = (m == 0) ? Qb : Vb;

        ull acc[8][2];
        #pragma unroll
        for (int r = 0; r < 8; ++r) { acc[r][0] = 0ull; acc[r][1] = 0ull; }

        for (int h2 = 0; h2 < 2; ++h2) {
            __syncthreads();
            {   // stage 32x128 half of W (16KB)
                const float4* s4 = (const float4*)(Wsrc + h2 * 4096);
                float4* d4 = (float4*)Ws;
                #pragma unroll
                for (int i = 0; i < 4; ++i) d4[tid + 256 * i] = s4[tid + 256 * i];
            }
            __syncthreads();

            const float* Xh = Xs + h2 * 32;
            #pragma unroll 2
            for (int e0 = 0; e0 < 32; e0 += 4) {
                ull w01[4], w23[4];
                #pragma unroll
                for (int k = 0; k < 4; ++k) {
                    float4 wv = *(const float4*)(Ws + (e0 + k) * CC + 4 * tx);
                    w01[k] = pack2(wv.x, wv.y);
                    w23[k] = pack2(wv.z, wv.w);
                }
                #pragma unroll
                for (int r = 0; r < 8; ++r) {
                    float4 xv = *(const float4*)(Xh + xoff[r] + e0);  // LDS.128 bcast
                    ull x0 = pack2(xv.x, xv.x), x1 = pack2(xv.y, xv.y);
                    ull x2 = pack2(xv.z, xv.z), x3 = pack2(xv.w, xv.w);
                    ffma2(acc[r][0], x0, w01[0]); ffma2(acc[r][1], x0, w23[0]);
                    ffma2(acc[r][0], x1, w01[1]); ffma2(acc[r][1], x1, w23[1]);
                    ffma2(acc[r][0], x2, w01[2]); ffma2(acc[r][1], x2, w23[2]);
                    ffma2(acc[r][0], x3, w01[3]); ffma2(acc[r][1], x3, w23[3]);
                }
            }
        }
        #pragma unroll
        for (int r = 0; r < 8; ++r) {
            if (frow[r] < FF) {
                float4 o;
                unpack2(acc[r][0], o.x, o.y);
                unpack2(acc[r][1], o.z, o.w);
                *(float4*)(dst + frow[r] * CC + 4 * tx) = o;
            }
        }

        if (m == 1) {
            __syncthreads();   // K fully written to Vb
            // pair-interleave K: Ktp[c>>1][2g + (c&1)] = K[g][c]
            for (int i = tid; i < FF * CC; i += 256) {
                int g = i >> 7, c = i & 127;
                Ktp[(c >> 1) * KTP_STRIDE + 2 * g + (c & 1)] = Vb[i];
            }
            // m=2's staging sync orders: transpose done before Vb overwritten
        }
    }
    __syncthreads();

    // ---- Scores + softmax, 24 tasks (h = t/6, 9-row group; grp 5 has 5 rows).
    // Lane owns g-pair (2*lane, 2*lane+1); valid lanes 0..24.
    ull res[3][9];
    {
        #pragma unroll
        for (int s = 0; s < 3; ++s) {
            const int t   = warp + 8 * s;
            const int h   = t / 6;
            const int grp = t - 6 * h;
            const int f0  = 9 * grp;

            const float* qp[9];
            #pragma unroll
            for (int r = 0; r < 9; ++r) {
                int f = f0 + r; if (f > FF - 1) f = FF - 1;   // clamp (dups discarded)
                qp[r] = Qb + f * CC + 32 * h;
            }

            ull accP[9], accQ[9];
            #pragma unroll
            for (int r = 0; r < 9; ++r) { accP[r] = 0ull; accQ[r] = 0ull; }

            const float* kbase = Ktp + (16 * h) * KTP_STRIDE + 4 * lane;
            #pragma unroll 2
            for (int d2 = 0; d2 < 16; ++d2) {
                float4 kv = *(const float4*)(kbase + d2 * KTP_STRIDE); // LDS.128 cf
                ull kT = pack2(kv.x, kv.y);   // (k[2l][d],   k[2l][d+1])
                ull kU = pack2(kv.z, kv.w);   // (k[2l+1][d], k[2l+1][d+1])
                #pragma unroll
                for (int r = 0; r < 9; ++r) {
                    ull qq = *(const ull*)(qp[r] + 2 * d2);  // LDS.64 bcast (q_d,q_d+1)
                    ffma2(accP[r], qq, kT);
                    ffma2(accQ[r], qq, kU);
                }
            }

            // softmax per row; pack A(2l), A(2l+1) into res
            #pragma unroll
            for (int r = 0; r < 9; ++r) {
                float pl, ph, ql, qh;
                unpack2(accP[r], pl, ph);
                unpack2(accQ[r], ql, qh);
                float se = pl + ph;   // score for g = 2*lane
                float so = ql + qh;   // score for g = 2*lane+1
                bool valid = (lane < 25);
                if (!valid) { se = -3.4e38f; so = -3.4e38f; }
                float mx = fmaxf(se, so);
                #pragma unroll
                for (int o = 16; o; o >>= 1) mx = fmaxf(mx, __shfl_xor_sync(0xffffffffu, mx, o));
                float e0 = valid ? __expf(se - mx) : 0.f;
                float e1 = valid ? __expf(so - mx) : 0.f;
                float su = e0 + e1;
                #pragma unroll
                for (int o = 16; o; o >>= 1) su += __shfl_xor_sync(0xffffffffu, su, o);
                float inv = 1.0f / su;
                res[s][r] = pack2(e0 * inv, e1 * inv);
            }
        }
    }
    __syncthreads();   // all Qb/Ktp reads done before Sb overwrites that region

    {
        #pragma unroll
        for (int s = 0; s < 3; ++s) {
            const int t   = warp + 8 * s;
            const int h   = t / 6;
            const int grp = t - 6 * h;
            const int f0  = 9 * grp;
            const int nr  = (grp == 5) ? 5 : 9;
            if (lane < 25) {
                #pragma unroll
                for (int r = 0; r < 9; ++r) {
                    if (r < nr)
                        *(ull*)(Sb + (h * FF + f0 + r) * S_STRIDE + 2 * lane) = res[s][r];
                }
            }
        }
    }
    __syncthreads();

    // ---- AV + R(=X@Wr) + ReLU. Thread owns col jj; rows fb, fb+2, ... (25).
    {
        const int jj = tid & 127;
        const int fb = tid >> 7;
        const int h  = jj >> 5;
        const float* Sh = Sb + h * FF * S_STRIDE;

        ull acc[25];
        #pragma unroll
        for (int i = 0; i < 25; ++i) acc[i] = 0ull;

        // AV main: g = 0..44 step 4 (float4 A broadcasts)
        for (int g4 = 0; g4 < 12; ++g4) {
            const int g = 4 * g4;
            ull vv01 = pack2(Vb[(g + 0) * CC + jj], Vb[(g + 1) * CC + jj]);
            ull vv23 = pack2(Vb[(g + 2) * CC + jj], Vb[(g + 3) * CC + jj]);
            #pragma unroll
            for (int i = 0; i < 25; ++i) {
                const int f = fb + 2 * i;
                float4 aa = *(const float4*)(Sh + f * S_STRIDE + g);  // LDS.128 bcast
                ffma2(acc[i], pack2(aa.x, aa.y), vv01);
                ffma2(acc[i], pack2(aa.z, aa.w), vv23);
            }
        }
        {   // tail g = 48,49
            ull vv = pack2(Vb[48 * CC + jj], Vb[49 * CC + jj]);
            #pragma unroll
            for (int i = 0; i < 25; ++i) {
                const int f = fb + 2 * i;
                ull aa = *(const ull*)(Sh + f * S_STRIDE + 48);
                ffma2(acc[i], aa, vv);
            }
        }

        // Residual: X @ Wr, staged in halves
        for (int h2 = 0; h2 < 2; ++h2) {
            __syncthreads();
            {
                const float4* s4 = (const float4*)(Wr + h2 * 4096);
                float4* d4 = (float4*)Ws;
                #pragma unroll
                for (int i2 = 0; i2 < 4; ++i2) d4[tid + 256 * i2] = s4[tid + 256 * i2];
            }
            __syncthreads();

            const float* Xh = Xs + h2 * 32;
            for (int e4 = 0; e4 < 8; ++e4) {
                const int e = 4 * e4;
                ull ww01 = pack2(Ws[(e + 0) * CC + jj], Ws[(e + 1) * CC + jj]);
                ull ww23 = pack2(Ws[(e + 2) * CC + jj], Ws[(e + 3) * CC + jj]);
                #pragma unroll
                for (int i = 0; i < 25; ++i) {
                    const int f = fb + 2 * i;
                    float4 xv = *(const float4*)(Xh + f * EE + e);   // LDS.128 bcast
                    ffma2(acc[i], pack2(xv.x, xv.y), ww01);
                    ffma2(acc[i], pack2(xv.z, xv.w), ww23);
                }
            }
        }

        float* outB = out + (size_t)b * (FF * CC);
        #pragma unroll
        for (int i = 0; i < 25; ++i) {
            const int f = fb + 2 * i;
            float lo, hi; unpack2(acc[i], lo, hi);
            outB[f * CC + jj] = fmaxf(lo + hi, 0.f);   // coalesced
        }
    }
}

extern "C" void kernel_launch(void* const* d_in, const int* in_sizes, int n_in,
                              void* d_out, int out_size)
{
    const float* X  = (const float*)d_in[0];
    const float* Wq = (const float*)d_in[1];
    const float* Wk = (const float*)d_in[2];
    const float* Wv = (const float*)d_in[3];
    const float* Wr = (const float*)d_in[4];
    float* out = (float*)d_out;

    cudaFuncSetAttribute(autoint_v3,
                         cudaFuncAttributeMaxDynamicSharedMemorySize, SMEM_BYTES);
    autoint_v3<<<BB, 256, SMEM_BYTES>>>(X, Wq, Wk, Wv, Wr, out);
}

// round 11
// speedup vs baseline: 1.7341x; 1.1458x over previous
#include <cuda_runtime.h>
#include <cuda_bf16.h>
#include <math.h>

// InteractingLayer (AutoInt): B=4096, F=50, E=64, H=4, D=32.
// v5: projections Q,K,V,R via mma.sync m16n8k16 bf16-split (f32 accum in regs,
// base-target tensor instructions -- tcgen05 is rejected by the harness's
// compute_103 PTX stage). Scalar scores/softmax/AV from v3 (proven).
// 2 batches/CTA (M=128, 100 valid), 512 threads, 1 CTA/SM, 231KB smem.

#define BB 4096
#define FF 50
#define EE 64
#define CC 128

typedef unsigned long long ull;
typedef unsigned short u16;
typedef unsigned int u32;

// ---- smem layout (float units) ----
// XHI bytes [0,18432) : bf16 [128][72];  XLO bytes [18432,36864)
#define WB_OFF  9216       // bytes 36864: WThi [128][72] bf16; WTlo at +18432
#define KTP_OFF 18432      // Ktp[2][64][104] = 13312
#define QB_OFF  31744      // Qb [2][50][130] = 13000
#define VB_OFF  44744      // Vb [2][50][130] = 13000
#define SMEM_FLOATS 57744
#define SMEM_BYTES (SMEM_FLOATS * 4)   // 230976 <= 232448
#define RB_OFF  0          // Rb [2][50][130] overlays X+W images (dead after R mma)
#define SB_OFF  18432      // Sb [2][4][50][52] = 20800 overlays Ktp+Qb (post-scores)
#define PBS 130
#define PBATCH 6500
#define KTP_STRIDE 104
#define KBATCH 6656
#define S_STRIDE 52
#define XW_STRIDE_B 144    // 72 bf16 rows for X and WT images

__device__ u16 g_Wimg[4][2 * 128 * 64];   // [w][hi/lo][n][k] bf16 of W^T

// ---- helpers ----
__device__ __forceinline__ u32 s2u32(const void* p) {
    u32 a; asm("{ .reg .u64 t; cvta.to.shared.u64 t, %1; cvt.u32.u64 %0, t; }" : "=r"(a) : "l"(p));
    return a;
}
__device__ __forceinline__ void ldsm4(u32* r, u32 a) {
    asm volatile("ldmatrix.sync.aligned.m8n8.x4.shared.b16 {%0,%1,%2,%3}, [%4];"
        : "=r"(r[0]), "=r"(r[1]), "=r"(r[2]), "=r"(r[3]) : "r"(a));
}
__device__ __forceinline__ void ldsm2(u32* r, u32 a) {
    asm volatile("ldmatrix.sync.aligned.m8n8.x2.shared.b16 {%0,%1}, [%2];"
        : "=r"(r[0]), "=r"(r[1]) : "r"(a));
}
__device__ __forceinline__ void mma_bf16(float* d, const u32* a, const u32* b) {
    asm volatile("mma.sync.aligned.m16n8k16.row.col.f32.bf16.bf16.f32 "
        "{%0,%1,%2,%3}, {%4,%5,%6,%7}, {%8,%9}, {%0,%1,%2,%3};"
        : "+f"(d[0]), "+f"(d[1]), "+f"(d[2]), "+f"(d[3])
        : "r"(a[0]), "r"(a[1]), "r"(a[2]), "r"(a[3]), "r"(b[0]), "r"(b[1]));
}
__device__ __forceinline__ ull pack2(float lo, float hi) {
    ull r; asm("mov.b64 %0,{%1,%2};" : "=l"(r) : "f"(lo), "f"(hi)); return r;
}
__device__ __forceinline__ void unpack2(ull v, float& lo, float& hi) {
    asm("mov.b64 {%0,%1},%2;" : "=f"(lo), "=f"(hi) : "l"(v));
}
__device__ __forceinline__ void ffma2(ull& d, ull a, ull b) {
    asm("fma.rn.f32x2 %0,%1,%2,%3;" : "=l"(d) : "l"(a), "l"(b), "l"(d));
}

// ---- prep: W^T bf16 hi|lo images in [n][k] layout (k contiguous) ----
__global__ void prep_w(const float* __restrict__ Wq, const float* __restrict__ Wk,
                       const float* __restrict__ Wv, const float* __restrict__ Wr)
{
    int idx = blockIdx.x * blockDim.x + threadIdx.x;   // 4*128*64 = 32768
    if (idx >= 32768) return;
    int w = idx >> 13, rem = idx & 8191;
    int n = rem >> 6, k = rem & 63;
    const float* W = (w == 0) ? Wq : (w == 1) ? Wk : (w == 2) ? Wv : Wr;
    float v = W[k * CC + n];
    __nv_bfloat16 h = __float2bfloat16(v);
    __nv_bfloat16 l = __float2bfloat16(v - __bfloat162float(h));
    g_Wimg[w][n * 64 + k]        = __bfloat16_as_ushort(h);
    g_Wimg[w][8192 + n * 64 + k] = __bfloat16_as_ushort(l);
}

__global__ void __launch_bounds__(512, 1)
autoint_v5(const float* __restrict__ X, float* __restrict__ out)
{
    extern __shared__ float sm[];
    const int tid  = threadIdx.x;
    const int bid  = blockIdx.x;           // batches 2*bid, 2*bid+1
    const int lane = tid & 31;
    const int wid  = tid >> 5;
    const u32 smb  = s2u32(sm);

    // ---- 1. build X bf16 hi|lo images [128][72] (rows >= 100 zeroed)
    {
        u16* XH = (u16*)sm;
        u16* XL = XH + 9216;
        const float* Xg = X + (size_t)(2 * bid) * (FF * EE);
        for (int i = tid; i < 8192; i += 512) {
            int r = i >> 6, k = i & 63;
            float v = (r < 100) ? Xg[r * EE + k] : 0.f;
            __nv_bfloat16 h = __float2bfloat16(v);
            __nv_bfloat16 l = __float2bfloat16(v - __bfloat162float(h));
            XH[r * 72 + k] = __bfloat16_as_ushort(h);
            XL[r * 72 + k] = __bfloat16_as_ushort(l);
        }
    }
    __syncthreads();

    // ---- 2. load A fragments once (reused for all 4 W): warp tile M rows 32*mg
    const int ng = wid & 3;                // cols 32*ng..+31
    const int mg = wid >> 2;               // rows 32*mg..+31
    u32 ahi[2][4][4], alo[2][4][4];
    {
        const int arow = (lane & 15);
        const u32 akc  = ((lane >> 4) << 3) * 2;   // byte offset 0 or 16
        const u32 xh = smb, xl = smb + 18432;
        #pragma unroll
        for (int mt = 0; mt < 2; ++mt) {
            const u32 rb = (u32)(32 * mg + 16 * mt + arow) * XW_STRIDE_B + akc;
            #pragma unroll
            for (int ks = 0; ks < 4; ++ks) {
                ldsm4(ahi[mt][ks], xh + rb + 32 * ks);
                ldsm4(alo[mt][ks], xl + rb + 32 * ks);
            }
        }
    }

    // ---- 3. four W stages: stage WT image, 96 MMAs/warp, drain to smem
    float dR[4][8];                        // held R outputs (w==3)
    const u32 wh = smb + WB_OFF * 4;       // WThi base (bytes)
    const u32 wl = wh + 18432;             // WTlo
    const int brow = (lane & 7);
    const u32 bkc  = (((lane >> 3) & 1) << 3) * 2;   // 0 or 16 bytes

    for (int w = 0; w < 4; ++w) {
        __syncthreads();                   // prior readers of WB done
        {
            const uint4* src = (const uint4*)g_Wimg[w];   // [2][128][8] uint4
            char* dst = (char*)sm + WB_OFF * 4;
            for (int i = tid; i < 2048; i += 512) {
                int s = i >> 10, n = (i >> 3) & 127, j = i & 7;
                *(uint4*)(dst + s * 18432 + n * XW_STRIDE_B + j * 16) = src[i];
            }
        }
        __syncthreads();

        #pragma unroll
        for (int nt = 0; nt < 4; ++nt) {
            float d0[4] = {0.f, 0.f, 0.f, 0.f};
            float d1[4] = {0.f, 0.f, 0.f, 0.f};
            const u32 rb = (u32)(32 * ng + 8 * nt + brow) * XW_STRIDE_B + bkc;
            #pragma unroll
            for (int ks = 0; ks < 4; ++ks) {
                u32 bh[2], bl[2];
                ldsm2(bh, wh + rb + 32 * ks);
                ldsm2(bl, wl + rb + 32 * ks);
                mma_bf16(d0, ahi[0][ks], bh);
                mma_bf16(d0, ahi[0][ks], bl);
                mma_bf16(d0, alo[0][ks], bh);
                mma_bf16(d1, ahi[1][ks], bh);
                mma_bf16(d1, ahi[1][ks], bl);
                mma_bf16(d1, alo[1][ks], bh);
            }
            if (w == 3) {
                #pragma unroll
                for (int j = 0; j < 4; ++j) { dR[nt][j] = d0[j]; dR[nt][4 + j] = d1[j]; }
            } else {
                const int n = 32 * ng + 8 * nt + 2 * (lane & 3);
                const int m = 32 * mg + (lane >> 2);
                #pragma unroll
                for (int q = 0; q < 4; ++q) {           // (mt, +8) x (c01, c23)
                    const int r = m + 16 * (q >> 1) + 8 * (q & 1);
                    const float va = (q >> 1) ? d1[2 * (q & 1)]     : d0[2 * (q & 1)];
                    const float vb = (q >> 1) ? d1[2 * (q & 1) + 1] : d0[2 * (q & 1) + 1];
                    if (r < 100) {
                        const int bt = (r >= 50), f = r - 50 * bt;
                        if (w == 1) {
                            float2* p = (float2*)(sm + KTP_OFF + bt * KBATCH
                                                  + (n >> 1) * KTP_STRIDE + 2 * f);
                            *p = make_float2(va, vb);
                        } else {
                            const int base = (w == 0) ? QB_OFF : VB_OFF;
                            float2* p = (float2*)(sm + base + bt * PBATCH + f * PBS + n);
                            *p = make_float2(va, vb);
                        }
                    }
                }
            }
        }
    }
    __syncthreads();                       // all WB/X reads done -> safe to overlay Rb
    {
        const int n = 32 * ng + 2 * (lane & 3);
        const int m = 32 * mg + (lane >> 2);
        #pragma unroll
        for (int nt = 0; nt < 4; ++nt) {
            #pragma unroll
            for (int q = 0; q < 4; ++q) {
                const int r = m + 16 * (q >> 1) + 8 * (q & 1);
                if (r < 100) {
                    const int bt = (r >= 50), f = r - 50 * bt;
                    float2* p = (float2*)(sm + RB_OFF + bt * PBATCH + f * PBS + n + 8 * nt);
                    *p = make_float2(dR[nt][4 * (q >> 1) + 2 * (q & 1)],
                                     dR[nt][4 * (q >> 1) + 2 * (q & 1) + 1]);
                }
            }
        }
    }
    __syncthreads();

    // ---- 4. scores + softmax in registers. 48 tasks = 2 batch x 4 h x 6 grp(9 rows).
    ull res[3][9];
    {
        #pragma unroll
        for (int s = 0; s < 3; ++s) {
            const int t   = wid + 16 * s;
            const int bt  = t / 24;
            const int rem = t - 24 * bt;
            const int h   = rem / 6;
            const int grp = rem - 6 * h;
            const int f0  = 9 * grp;

            const float* qp[9];
            #pragma unroll
            for (int r = 0; r < 9; ++r) {
                int f = f0 + r; if (f > FF - 1) f = FF - 1;
                qp[r] = sm + QB_OFF + bt * PBATCH + f * PBS + 32 * h;
            }
            ull accP[9], accQ[9];
            #pragma unroll
            for (int r = 0; r < 9; ++r) { accP[r] = 0ull; accQ[r] = 0ull; }

            const float* kbase = sm + KTP_OFF + bt * KBATCH + (16 * h) * KTP_STRIDE + 4 * lane;
            #pragma unroll 2
            for (int d2 = 0; d2 < 16; ++d2) {
                float4 kv = *(const float4*)(kbase + d2 * KTP_STRIDE);
                ull kT = pack2(kv.x, kv.y);
                ull kU = pack2(kv.z, kv.w);
                #pragma unroll
                for (int r = 0; r < 9; ++r) {
                    ull qq = *(const ull*)(qp[r] + 2 * d2);
                    ffma2(accP[r], qq, kT);
                    ffma2(accQ[r], qq, kU);
                }
            }
            #pragma unroll
            for (int r = 0; r < 9; ++r) {
                float pl, ph, ql, qh;
                unpack2(accP[r], pl, ph);
                unpack2(accQ[r], ql, qh);
                float se = pl + ph, so = ql + qh;
                bool ok = (lane < 25);
                if (!ok) { se = -3.4e38f; so = -3.4e38f; }
                float mx = fmaxf(se, so);
                #pragma unroll
                for (int o = 16; o; o >>= 1) mx = fmaxf(mx, __shfl_xor_sync(0xffffffffu, mx, o));
                float e0 = ok ? __expf(se - mx) : 0.f;
                float e1 = ok ? __expf(so - mx) : 0.f;
                float su = e0 + e1;
                #pragma unroll
                for (int o = 16; o; o >>= 1) su += __shfl_xor_sync(0xffffffffu, su, o);
                float inv = 1.0f / su;
                res[s][r] = pack2(e0 * inv, e1 * inv);
            }
        }
    }
    __syncthreads();   // all Qb/Ktp reads done before Sb overlays them

    {
        #pragma unroll
        for (int s = 0; s < 3; ++s) {
            const int t   = wid + 16 * s;
            const int bt  = t / 24;
            const int rem = t - 24 * bt;
            const int h   = rem / 6;
            const int grp = rem - 6 * h;
            const int f0  = 9 * grp;
            const int nr  = (grp == 5) ? 5 : 9;
            if (lane < 25) {
                #pragma unroll
                for (int r = 0; r < 9; ++r) {
                    if (r < nr)
                        *(ull*)(sm + SB_OFF + (((bt * 4 + h) * FF) + f0 + r) * S_STRIDE + 2 * lane)
                            = res[s][r];
                }
            }
        }
    }
    __syncthreads();

    // ---- 5. AV + R + ReLU. thread = (batch bb, col jj, row parity fb); 25 rows each.
    {
        const int bb = tid >> 8;
        const int jj = tid & 127;
        const int fb = (tid >> 7) & 1;
        const int h  = jj >> 5;
        const float* Sh = sm + SB_OFF + ((bb * 4 + h) * FF) * S_STRIDE;
        const float* Vp = sm + VB_OFF + bb * PBATCH;
        const float* Rp = sm + RB_OFF + bb * PBATCH;

        ull acc[25];
        #pragma unroll
        for (int i = 0; i < 25; ++i) acc[i] = 0ull;

        for (int g4 = 0; g4 < 12; ++g4) {
            const int g = 4 * g4;
            ull vv01 = pack2(Vp[(g + 0) * PBS + jj], Vp[(g + 1) * PBS + jj]);
            ull vv23 = pack2(Vp[(g + 2) * PBS + jj], Vp[(g + 3) * PBS + jj]);
            #pragma unroll
            for (int i = 0; i < 25; ++i) {
                const int f = fb + 2 * i;
                float4 aa = *(const float4*)(Sh + f * S_STRIDE + g);
                ffma2(acc[i], pack2(aa.x, aa.y), vv01);
                ffma2(acc[i], pack2(aa.z, aa.w), vv23);
            }
        }
        {
            ull vv = pack2(Vp[48 * PBS + jj], Vp[49 * PBS + jj]);
            #pragma unroll
            for (int i = 0; i < 25; ++i) {
                const int f = fb + 2 * i;
                ull aa = *(const ull*)(Sh + f * S_STRIDE + 48);
                ffma2(acc[i], aa, vv);
            }
        }

        float* outB = out + (size_t)(2 * bid + bb) * (FF * CC);
        #pragma unroll
        for (int i = 0; i < 25; ++i) {
            const int f = fb + 2 * i;
            float lo, hi; unpack2(acc[i], lo, hi);
            outB[f * CC + jj] = fmaxf(lo + hi + Rp[f * PBS + jj], 0.f);
        }
    }
}

extern "C" void kernel_launch(void* const* d_in, const int* in_sizes, int n_in,
                              void* d_out, int out_size)
{
    const float* X  = (const float*)d_in[0];
    const float* Wq = (const float*)d_in[1];
    const float* Wk = (const float*)d_in[2];
    const float* Wv = (const float*)d_in[3];
    const float* Wr = (const float*)d_in[4];
    float* out = (float*)d_out;

    prep_w<<<64, 512>>>(Wq, Wk, Wv, Wr);
    cudaFuncSetAttribute(autoint_v5,
                         cudaFuncAttributeMaxDynamicSharedMemorySize, SMEM_BYTES);
    autoint_v5<<<BB / 2, 512, SMEM_BYTES>>>(X, out);
}

// round 12
// speedup vs baseline: 1.7698x; 1.0206x over previous
#include <cuda_runtime.h>
#include <cuda_bf16.h>

// InteractingLayer (AutoInt): B=4096, F=50, E=64, H=4, D=32.
// v6: EVERYTHING on tensor cores (mma.sync m16n8k16 bf16-split):
//   proj Q,K,V,R -> scores Q@K^T -> (fragment softmax) -> A@V.
// A-fragments for AV built in registers from score D-fragments (no smem S).
// Residual R written to gmem at proj time; epilogue does relu(AV + out).
// 2 batches/CTA (M=128), 512 threads, 1 CTA/SM, 213KB smem.

#define BB 4096
#define FF 50
#define EE 64
#define CC 128

typedef unsigned long long ull;
typedef unsigned short u16;
typedef unsigned int u32;

// ---- smem byte offsets ----
// region0 [0, 73728): proj phase = XH|XL images + WH|WL staging; then VtH|VtL
#define XH_B 0
#define XL_B 18432
#define WH_B 36864
#define WL_B 55296
#define VTH_B 0
#define VTL_B 36864
#define VT_BT 18432        // per-batch Vt: [128 n][72 g] bf16
#define QH_B 73728         // Q image [128][136] bf16
#define QL_B 108544
#define KH_B 143360
#define KL_B 178176
#define SMEM_BYTES 212992
#define QK_STRIDE 272      // bytes/row (136 bf16) -> conflict-free ldmatrix
#define XW_STRIDE 144
#define VT_STRIDE 144

__device__ u16 g_Wimg[4][2 * 128 * 64];   // [w][hi|lo][n][k] bf16 of W^T

// ---- helpers ----
__device__ __forceinline__ u32 s2u32(const void* p) {
    u32 a; asm("{ .reg .u64 t; cvta.to.shared.u64 t, %1; cvt.u32.u64 %0, t; }" : "=r"(a) : "l"(p));
    return a;
}
__device__ __forceinline__ void ldsm4(u32* r, u32 a) {
    asm volatile("ldmatrix.sync.aligned.m8n8.x4.shared.b16 {%0,%1,%2,%3}, [%4];"
        : "=r"(r[0]), "=r"(r[1]), "=r"(r[2]), "=r"(r[3]) : "r"(a));
}
__device__ __forceinline__ void ldsm2(u32* r, u32 a) {
    asm volatile("ldmatrix.sync.aligned.m8n8.x2.shared.b16 {%0,%1}, [%2];"
        : "=r"(r[0]), "=r"(r[1]) : "r"(a));
}
__device__ __forceinline__ void mma_bf16(float* d, const u32* a, const u32* b) {
    asm volatile("mma.sync.aligned.m16n8k16.row.col.f32.bf16.bf16.f32 "
        "{%0,%1,%2,%3}, {%4,%5,%6,%7}, {%8,%9}, {%0,%1,%2,%3};"
        : "+f"(d[0]), "+f"(d[1]), "+f"(d[2]), "+f"(d[3])
        : "r"(a[0]), "r"(a[1]), "r"(a[2]), "r"(a[3]), "r"(b[0]), "r"(b[1]));
}
// pack (lo, hi) floats -> bf16x2 (lo in low 16 bits; PTX: first src -> upper)
__device__ __forceinline__ u32 cvt_bf2(float lo, float hi) {
    u32 r; asm("cvt.rn.bf16x2.f32 %0, %1, %2;" : "=r"(r) : "f"(hi), "f"(lo));
    return r;
}

// ---- prep: W^T bf16 hi|lo images in [n][k] layout ----
__global__ void prep_w(const float* __restrict__ Wq, const float* __restrict__ Wk,
                       const float* __restrict__ Wv, const float* __restrict__ Wr)
{
    int idx = blockIdx.x * blockDim.x + threadIdx.x;   // 4*128*64
    if (idx >= 32768) return;
    int w = idx >> 13, rem = idx & 8191;
    int n = rem >> 6, k = rem & 63;
    const float* W = (w == 0) ? Wq : (w == 1) ? Wk : (w == 2) ? Wv : Wr;
    float v = W[k * CC + n];
    __nv_bfloat16 h = __float2bfloat16(v);
    __nv_bfloat16 l = __float2bfloat16(v - __bfloat162float(h));
    g_Wimg[w][n * 64 + k]        = __bfloat16_as_ushort(h);
    g_Wimg[w][8192 + n * 64 + k] = __bfloat16_as_ushort(l);
}

__global__ void __launch_bounds__(512, 1)
autoint_v6(const float* __restrict__ X, float* __restrict__ out)
{
    extern __shared__ float sm[];
    char* smc = (char*)sm;
    const int tid  = threadIdx.x;
    const int bid  = blockIdx.x;              // batches 2*bid, 2*bid+1
    const int lane = tid & 31;
    const int wid  = tid >> 5;
    const int l3   = lane & 3;
    const u32 smb  = s2u32(sm);

    // ---- 1. X bf16 hi|lo images [128][72] (rows >= 100 zeroed)
    {
        u16* XH = (u16*)(smc + XH_B);
        u16* XL = (u16*)(smc + XL_B);
        const float* Xg = X + (size_t)(2 * bid) * (FF * EE);
        for (int i = tid; i < 8192; i += 512) {
            int r = i >> 6, k = i & 63;
            float v = (r < 100) ? Xg[r * EE + k] : 0.f;
            u16 h = __bfloat16_as_ushort(__float2bfloat16(v));
            u16 l = __bfloat16_as_ushort(__float2bfloat16(v - __uint_as_float((u32)h << 16)));
            XH[r * 72 + k] = h;
            XL[r * 72 + k] = l;
        }
    }
    __syncthreads();

    // ---- 2. A fragments (X) once; warp tile = rows 32*mg, cols 32*ng
    const int ng = wid & 3;
    const int mg = wid >> 2;
    u32 ahi[2][4][4], alo[2][4][4];
    #pragma unroll
    for (int mt = 0; mt < 2; ++mt) {
        const u32 rb = (u32)(32 * mg + 16 * mt + (lane & 15)) * XW_STRIDE + 16 * (lane >> 4);
        #pragma unroll
        for (int ks = 0; ks < 4; ++ks) {
            ldsm4(ahi[mt][ks], smb + XH_B + rb + 32 * ks);
            ldsm4(alo[mt][ks], smb + XL_B + rb + 32 * ks);
        }
    }

    // ---- 3. stages Q(0), K(1), R(2: ->gmem), V(3: hold regs)
    float dVreg[4][8];
    const int brow = lane & 7;
    const u32 bkc  = 16 * ((lane >> 3) & 1);
    const int m0   = 32 * mg + (lane >> 2);

    for (int s = 0; s < 4; ++s) {
        const int wi = (s == 2) ? 3 : ((s == 3) ? 2 : s);   // g_Wimg index
        __syncthreads();
        {   // stage W^T hi|lo into WB
            const uint4* src = (const uint4*)g_Wimg[wi];
            for (int i = tid; i < 2048; i += 512) {
                int ss = i >> 10, n = (i >> 3) & 127, j = i & 7;
                *(uint4*)(smc + WH_B + ss * 18432 + n * XW_STRIDE + j * 16) = src[i];
            }
        }
        __syncthreads();

        #pragma unroll
        for (int nt = 0; nt < 4; ++nt) {
            float d0[4] = {0.f, 0.f, 0.f, 0.f};
            float d1[4] = {0.f, 0.f, 0.f, 0.f};
            const u32 rb = (u32)(32 * ng + 8 * nt + brow) * XW_STRIDE + bkc;
            #pragma unroll
            for (int ks = 0; ks < 4; ++ks) {
                u32 bh[2], bl[2];
                ldsm2(bh, smb + WH_B + rb + 32 * ks);
                ldsm2(bl, smb + WL_B + rb + 32 * ks);
                mma_bf16(d0, ahi[0][ks], bh);
                mma_bf16(d0, ahi[0][ks], bl);
                mma_bf16(d0, alo[0][ks], bh);
                mma_bf16(d1, ahi[1][ks], bh);
                mma_bf16(d1, ahi[1][ks], bl);
                mma_bf16(d1, alo[1][ks], bh);
            }
            const int nb = 32 * ng + 8 * nt + 2 * l3;
            if (s <= 1) {
                // drain to bf16 hi|lo image (rows 0..127 all written)
                const u32 hB = (s == 0) ? QH_B : KH_B;
                const u32 lB = (s == 0) ? QL_B : KL_B;
                #pragma unroll
                for (int q = 0; q < 4; ++q) {
                    int r = m0 + 16 * (q >> 1) + 8 * (q & 1);
                    float va = (q >> 1) ? d1[2 * (q & 1)]     : d0[2 * (q & 1)];
                    float vb = (q >> 1) ? d1[2 * (q & 1) + 1] : d0[2 * (q & 1) + 1];
                    u32 hp = cvt_bf2(va, vb);
                    u32 lp = cvt_bf2(va - __uint_as_float(hp << 16),
                                     vb - __uint_as_float(hp & 0xffff0000u));
                    *(u32*)(smc + hB + (u32)r * QK_STRIDE + nb * 2) = hp;
                    *(u32*)(smc + lB + (u32)r * QK_STRIDE + nb * 2) = lp;
                }
            } else if (s == 2) {
                // residual R -> gmem fp32 (epilogue RMWs it)
                #pragma unroll
                for (int q = 0; q < 4; ++q) {
                    int r = m0 + 16 * (q >> 1) + 8 * (q & 1);
                    if (r < 100) {
                        int bt = (r >= 50), f = r - 50 * bt;
                        float2 v;
                        v.x = (q >> 1) ? d1[2 * (q & 1)]     : d0[2 * (q & 1)];
                        v.y = (q >> 1) ? d1[2 * (q & 1) + 1] : d0[2 * (q & 1) + 1];
                        *(float2*)(out + (size_t)(2 * bid + bt) * (FF * CC) + f * CC + nb) = v;
                    }
                }
            } else {
                #pragma unroll
                for (int j = 0; j < 4; ++j) { dVreg[nt][j] = d0[j]; dVreg[nt][4 + j] = d1[j]; }
            }
        }
    }
    __syncthreads();   // all X/WB readers done -> region0 becomes Vt

    // ---- 4. drain V^T bf16 hi|lo into Vt[bt][n][g]; zero pad g in [50,64)
    {
        #pragma unroll
        for (int nt = 0; nt < 4; ++nt) {
            #pragma unroll
            for (int q = 0; q < 4; ++q) {
                int r = m0 + 16 * (q >> 1) + 8 * (q & 1);
                if (r < 100) {
                    int bt = (r >= 50), g = r - 50 * bt;
                    int n0 = 32 * ng + 8 * nt + 2 * l3;
                    float va = dVreg[nt][4 * (q >> 1) + 2 * (q & 1)];
                    float vb = dVreg[nt][4 * (q >> 1) + 2 * (q & 1) + 1];
                    u16 ha = __bfloat16_as_ushort(__float2bfloat16(va));
                    u16 hb = __bfloat16_as_ushort(__float2bfloat16(vb));
                    u16 la = __bfloat16_as_ushort(__float2bfloat16(va - __uint_as_float((u32)ha << 16)));
                    u16 lb = __bfloat16_as_ushort(__float2bfloat16(vb - __uint_as_float((u32)hb << 16)));
                    u32 base = (u32)bt * VT_BT + (u32)g * 2;
                    *(u16*)(smc + VTH_B + base + (u32)n0 * VT_STRIDE)       = ha;
                    *(u16*)(smc + VTH_B + base + (u32)(n0 + 1) * VT_STRIDE) = hb;
                    *(u16*)(smc + VTL_B + base + (u32)n0 * VT_STRIDE)       = la;
                    *(u16*)(smc + VTL_B + base + (u32)(n0 + 1) * VT_STRIDE) = lb;
                }
            }
        }
        for (int i = tid; i < 2 * 128 * 14; i += 512) {
            int bt = i / 1792, rem = i % 1792;
            int n = rem / 14, g = 50 + rem % 14;
            u32 a = (u32)bt * VT_BT + (u32)n * VT_STRIDE + (u32)g * 2;
            *(u16*)(smc + VTH_B + a) = 0;
            *(u16*)(smc + VTL_B + a) = 0;
        }
    }

    // ---- 5. scores: task (bt,h) = wid>>1; warp rows 32*sub..+31 (local), N=64, K=32
    const int task = wid >> 1;
    const int sub  = wid & 1;
    const int sbt  = task >> 2;
    const int sh   = task & 3;

    float dS[2][8][4];
    #pragma unroll
    for (int mt = 0; mt < 2; ++mt)
        #pragma unroll
        for (int nt = 0; nt < 8; ++nt)
            #pragma unroll
            for (int j = 0; j < 4; ++j) dS[mt][nt][j] = 0.f;

    {
        const u32 qr = (u32)(50 * sbt + 32 * sub);
        const int ii = lane >> 3;
        #pragma unroll
        for (int kb = 0; kb < 2; ++kb) {
            u32 aH[2][4], aL[2][4];
            #pragma unroll
            for (int mt = 0; mt < 2; ++mt) {
                u32 ad = smb + QH_B + (qr + 16 * mt + (lane & 15)) * QK_STRIDE
                       + 64 * sh + kb * 32 + 16 * (lane >> 4);
                ldsm4(aH[mt], ad);
                ldsm4(aL[mt], ad + (QL_B - QH_B));
            }
            u32 bH[16], bL[16];
            #pragma unroll
            for (int p = 0; p < 4; ++p) {
                u32 kd = smb + KH_B
                       + (u32)(50 * sbt + 8 * (2 * p + (ii >> 1)) + (lane & 7)) * QK_STRIDE
                       + 64 * sh + kb * 32 + 16 * (ii & 1);
                ldsm4(&bH[4 * p], kd);
                ldsm4(&bL[4 * p], kd + (KL_B - KH_B));
            }
            #pragma unroll
            for (int mt = 0; mt < 2; ++mt)
                #pragma unroll
                for (int nt = 0; nt < 8; ++nt) {
                    mma_bf16(dS[mt][nt], aH[mt], &bH[2 * nt]);
                    mma_bf16(dS[mt][nt], aL[mt], &bH[2 * nt]);
                    mma_bf16(dS[mt][nt], aH[mt], &bL[2 * nt]);
                }
        }
    }

    // ---- 6. softmax in fragments (rows within warp; cols: quad + 8 n-tiles)
    #pragma unroll
    for (int mt = 0; mt < 2; ++mt)
        #pragma unroll
        for (int qq = 0; qq < 2; ++qq) {
            float mx = -3.4e38f;
            #pragma unroll
            for (int nt = 0; nt < 8; ++nt)
                #pragma unroll
                for (int c = 0; c < 2; ++c) {
                    bool ok = (nt < 6) || (nt == 6 && l3 == 0);   // col < 50
                    if (ok) mx = fmaxf(mx, dS[mt][nt][2 * qq + c]);
                }
            mx = fmaxf(mx, __shfl_xor_sync(0xffffffffu, mx, 1));
            mx = fmaxf(mx, __shfl_xor_sync(0xffffffffu, mx, 2));
            float su = 0.f;
            #pragma unroll
            for (int nt = 0; nt < 8; ++nt)
                #pragma unroll
                for (int c = 0; c < 2; ++c) {
                    bool ok = (nt < 6) || (nt == 6 && l3 == 0);
                    float e = ok ? __expf(dS[mt][nt][2 * qq + c] - mx) : 0.f;
                    dS[mt][nt][2 * qq + c] = e;
                    su += e;
                }
            su += __shfl_xor_sync(0xffffffffu, su, 1);
            su += __shfl_xor_sync(0xffffffffu, su, 2);
            float inv = 1.0f / su;
            #pragma unroll
            for (int nt = 0; nt < 8; ++nt) {
                dS[mt][nt][2 * qq]     *= inv;
                dS[mt][nt][2 * qq + 1] *= inv;
            }
        }

    // ---- 7. repack A (attn) D-frags -> bf16 hi|lo A-frags in registers
    u32 pHf[4][2][4], pLf[4][2][4];
    #pragma unroll
    for (int kb2 = 0; kb2 < 4; ++kb2)
        #pragma unroll
        for (int mt = 0; mt < 2; ++mt)
            #pragma unroll
            for (int j = 0; j < 4; ++j) {
                int nt = 2 * kb2 + (j >> 1);
                float x0 = dS[mt][nt][2 * (j & 1)];
                float x1 = dS[mt][nt][2 * (j & 1) + 1];
                u32 hp = cvt_bf2(x0, x1);
                pHf[kb2][mt][j] = hp;
                pLf[kb2][mt][j] = cvt_bf2(x0 - __uint_as_float(hp << 16),
                                          x1 - __uint_as_float(hp & 0xffff0000u));
            }

    __syncthreads();   // Vt fully written/zero-padded before AV reads

    // ---- 8. AV: M=32 (warp rows), N=32 (d), K=64 (g), 3 chains
    float dV[2][4][4];
    #pragma unroll
    for (int mt = 0; mt < 2; ++mt)
        #pragma unroll
        for (int nt = 0; nt < 4; ++nt)
            #pragma unroll
            for (int j = 0; j < 4; ++j) dV[mt][nt][j] = 0.f;
    {
        const int ii = lane >> 3;
        #pragma unroll
        for (int kb2 = 0; kb2 < 4; ++kb2) {
            u32 bH2[8], bL2[8];
            #pragma unroll
            for (int p = 0; p < 2; ++p) {
                u32 vd = smb + VTH_B + (u32)sbt * VT_BT
                       + (u32)(32 * sh + 8 * (2 * p + (ii >> 1)) + (lane & 7)) * VT_STRIDE
                       + kb2 * 32 + 16 * (ii & 1);
                ldsm4(&bH2[4 * p], vd);
                ldsm4(&bL2[4 * p], vd + (VTL_B - VTH_B));
            }
            #pragma unroll
            for (int mt = 0; mt < 2; ++mt)
                #pragma unroll
                for (int nt = 0; nt < 4; ++nt) {
                    mma_bf16(dV[mt][nt], pHf[kb2][mt], &bH2[2 * nt]);
                    mma_bf16(dV[mt][nt], pLf[kb2][mt], &bH2[2 * nt]);
                    mma_bf16(dV[mt][nt], pHf[kb2][mt], &bL2[2 * nt]);
                }
        }
    }

    // ---- 9. epilogue: out = relu(AV + R)  (R pre-stored in out by stage 2)
    {
        float* outB = out + (size_t)(2 * bid + sbt) * (FF * CC);
        #pragma unroll
        for (int mt = 0; mt < 2; ++mt)
            #pragma unroll
            for (int qq = 0; qq < 2; ++qq) {
                int fl = 32 * sub + 16 * mt + 8 * qq + (lane >> 2);
                if (fl < 50) {
                    #pragma unroll
                    for (int nt = 0; nt < 4; ++nt) {
                        int col = 32 * sh + 8 * nt + 2 * l3;
                        float2* p = (float2*)(outB + fl * CC + col);
                        float2 rv = *p;
                        float2 o;
                        o.x = fmaxf(dV[mt][nt][2 * qq]     + rv.x, 0.f);
                        o.y = fmaxf(dV[mt][nt][2 * qq + 1] + rv.y, 0.f);
                        *p = o;
                    }
                }
            }
    }
}

extern "C" void kernel_launch(void* const* d_in, const int* in_sizes, int n_in,
                              void* d_out, int out_size)
{
    const float* X  = (const float*)d_in[0];
    const float* Wq = (const float*)d_in[1];
    const float* Wk = (const float*)d_in[2];
    const float* Wv = (const float*)d_in[3];
    const float* Wr = (const float*)d_in[4];
    float* out = (float*)d_out;

    prep_w<<<64, 512>>>(Wq, Wk, Wv, Wr);
    cudaFuncSetAttribute(autoint_v6,
                         cudaFuncAttributeMaxDynamicSharedMemorySize, SMEM_BYTES);
    autoint_v6<<<BB / 2, 512, SMEM_BYTES>>>(X, out);
}

// round 13
// speedup vs baseline: 2.5309x; 1.4301x over previous
#include <cuda_runtime.h>
#include <cuda_bf16.h>

// InteractingLayer (AutoInt): B=4096, F=50, E=64, H=4, D=32.
// v7 = v6 (all-tensor mma.sync bf16-split pipeline) +
//   - cp.async double-buffered W staging (buffer 1 overlays dead X images)
//   - register-pressure restructure in scores/AV (p-loop B loads, lazy repack)
// 2 batches/CTA (M=128), 512 threads, 1 CTA/SM, 213KB smem.

#define BB 4096
#define FF 50
#define EE 64
#define CC 128

typedef unsigned long long ull;
typedef unsigned short u16;
typedef unsigned int u32;

// ---- smem byte offsets ----
// region0 [0, 73728):
//   phase A: XH|XL images [0,36864) + W buf0 [36864,73728)
//   phase B: W buf1 overlays [0,36864) (X dead after A-frag load)
//   phase C: VtH [0,36864) | VtL [36864,73728)
#define XH_B 0
#define XL_B 18432
#define WB0_B 36864        // stage buf 0 (hi; lo at +18432)
#define WB1_B 0            // stage buf 1 (hi; lo at +18432)
#define VTH_B 0
#define VTL_B 36864
#define VT_BT 18432        // per-batch Vt: [128 n][72 g] bf16
#define QH_B 73728         // Q image [128][136] bf16
#define QL_B 108544
#define KH_B 143360
#define KL_B 178176
#define SMEM_BYTES 212992
#define QK_STRIDE 272
#define XW_STRIDE 144
#define VT_STRIDE 144

__device__ u16 g_Wimg[4][2 * 128 * 64];   // [w][hi|lo][n][k] bf16 of W^T

// ---- helpers ----
__device__ __forceinline__ u32 s2u32(const void* p) {
    u32 a; asm("{ .reg .u64 t; cvta.to.shared.u64 t, %1; cvt.u32.u64 %0, t; }" : "=r"(a) : "l"(p));
    return a;
}
__device__ __forceinline__ void ldsm4(u32* r, u32 a) {
    asm volatile("ldmatrix.sync.aligned.m8n8.x4.shared.b16 {%0,%1,%2,%3}, [%4];"
        : "=r"(r[0]), "=r"(r[1]), "=r"(r[2]), "=r"(r[3]) : "r"(a));
}
__device__ __forceinline__ void ldsm2(u32* r, u32 a) {
    asm volatile("ldmatrix.sync.aligned.m8n8.x2.shared.b16 {%0,%1}, [%2];"
        : "=r"(r[0]), "=r"(r[1]) : "r"(a));
}
__device__ __forceinline__ void mma_bf16(float* d, const u32* a, const u32* b) {
    asm volatile("mma.sync.aligned.m16n8k16.row.col.f32.bf16.bf16.f32 "
        "{%0,%1,%2,%3}, {%4,%5,%6,%7}, {%8,%9}, {%0,%1,%2,%3};"
        : "+f"(d[0]), "+f"(d[1]), "+f"(d[2]), "+f"(d[3])
        : "r"(a[0]), "r"(a[1]), "r"(a[2]), "r"(a[3]), "r"(b[0]), "r"(b[1]));
}
__device__ __forceinline__ u32 cvt_bf2(float lo, float hi) {
    u32 r; asm("cvt.rn.bf16x2.f32 %0, %1, %2;" : "=r"(r) : "f"(hi), "f"(lo));
    return r;
}
__device__ __forceinline__ void cp16(u32 dst, const void* src) {
    asm volatile("cp.async.cg.shared.global [%0], [%1], 16;" :: "r"(dst), "l"(src) : "memory");
}
#define CP_COMMIT() asm volatile("cp.async.commit_group;" ::: "memory")
#define CP_WAIT(n)  asm volatile("cp.async.wait_group %0;" :: "n"(n) : "memory")

// issue one W stage (32KB) into smem buffer hiB via cp.async (4 chunks/thread)
__device__ __forceinline__ void issue_w(const u16* img, u32 smb, u32 hiB, int tid) {
    const char* src = (const char*)img;
    #pragma unroll
    for (int v = 0; v < 4; ++v) {
        int i = tid + 512 * v;
        int ss = i >> 10, n = (i >> 3) & 127, j = i & 7;
        cp16(smb + hiB + (u32)ss * 18432 + (u32)n * XW_STRIDE + (u32)j * 16,
             src + (size_t)i * 16);
    }
}

// ---- prep: W^T bf16 hi|lo images in [n][k] layout ----
__global__ void prep_w(const float* __restrict__ Wq, const float* __restrict__ Wk,
                       const float* __restrict__ Wv, const float* __restrict__ Wr)
{
    int idx = blockIdx.x * blockDim.x + threadIdx.x;
    if (idx >= 32768) return;
    int w = idx >> 13, rem = idx & 8191;
    int n = rem >> 6, k = rem & 63;
    const float* W = (w == 0) ? Wq : (w == 1) ? Wk : (w == 2) ? Wv : Wr;
    float v = W[k * CC + n];
    __nv_bfloat16 h = __float2bfloat16(v);
    __nv_bfloat16 l = __float2bfloat16(v - __bfloat162float(h));
    g_Wimg[w][n * 64 + k]        = __bfloat16_as_ushort(h);
    g_Wimg[w][8192 + n * 64 + k] = __bfloat16_as_ushort(l);
}

__global__ void __launch_bounds__(512, 1)
autoint_v7(const float* __restrict__ X, float* __restrict__ out)
{
    extern __shared__ float sm[];
    char* smc = (char*)sm;
    const int tid  = threadIdx.x;
    const int bid  = blockIdx.x;              // batches 2*bid, 2*bid+1
    const int lane = tid & 31;
    const int wid  = tid >> 5;
    const int l3   = lane & 3;
    const u32 smb  = s2u32(sm);

    // stage order: s0=Q(img0)->buf0, s1=K(img1)->buf1, s2=R(img3)->buf0, s3=V(img2)->buf1
    const int WIMG[4] = {0, 1, 3, 2};
    const u32 BUFB[4] = {WB0_B, WB1_B, WB0_B, WB1_B};

    // ---- 0. prefetch W stage 0 (overlaps X image build)
    issue_w(g_Wimg[WIMG[0]], smb, BUFB[0], tid);
    CP_COMMIT();

    // ---- 1. X bf16 hi|lo images [128][72] (rows >= 100 zeroed)
    {
        u16* XH = (u16*)(smc + XH_B);
        u16* XL = (u16*)(smc + XL_B);
        const float* Xg = X + (size_t)(2 * bid) * (FF * EE);
        for (int i = tid; i < 8192; i += 512) {
            int r = i >> 6, k = i & 63;
            float v = (r < 100) ? Xg[r * EE + k] : 0.f;
            u16 h = __bfloat16_as_ushort(__float2bfloat16(v));
            u16 l = __bfloat16_as_ushort(__float2bfloat16(v - __uint_as_float((u32)h << 16)));
            XH[r * 72 + k] = h;
            XL[r * 72 + k] = l;
        }
    }
    __syncthreads();

    // ---- 2. A fragments (X) once; warp tile = rows 32*mg, cols 32*ng
    const int ng = wid & 3;
    const int mg = wid >> 2;
    u32 ahi[2][4][4], alo[2][4][4];
    #pragma unroll
    for (int mt = 0; mt < 2; ++mt) {
        const u32 rb = (u32)(32 * mg + 16 * mt + (lane & 15)) * XW_STRIDE + 16 * (lane >> 4);
        #pragma unroll
        for (int ks = 0; ks < 4; ++ks) {
            ldsm4(ahi[mt][ks], smb + XH_B + rb + 32 * ks);
            ldsm4(alo[mt][ks], smb + XL_B + rb + 32 * ks);
        }
    }
    __syncthreads();                // X images dead -> buf1 region free

    // prefetch W stage 1 into buf1
    issue_w(g_Wimg[WIMG[1]], smb, BUFB[1], tid);
    CP_COMMIT();

    // ---- 3. stages Q(0), K(1), R(2 -> gmem), V(3 -> regs)
    float dVreg[4][8];
    const int brow = lane & 7;
    const u32 bkc  = 16 * ((lane >> 3) & 1);
    const int m0   = 32 * mg + (lane >> 2);

    for (int s = 0; s < 4; ++s) {
        if (s == 3) { CP_WAIT(0); } else { CP_WAIT(1); }
        __syncthreads();            // buf[s&1] fully landed for all threads

        const u32 whB = BUFB[s];
        #pragma unroll
        for (int nt = 0; nt < 4; ++nt) {
            float d0[4] = {0.f, 0.f, 0.f, 0.f};
            float d1[4] = {0.f, 0.f, 0.f, 0.f};
            const u32 rb = (u32)(32 * ng + 8 * nt + brow) * XW_STRIDE + bkc;
            #pragma unroll
            for (int ks = 0; ks < 4; ++ks) {
                u32 bh[2], bl[2];
                ldsm2(bh, smb + whB + rb + 32 * ks);
                ldsm2(bl, smb + whB + 18432 + rb + 32 * ks);
                mma_bf16(d0, ahi[0][ks], bh);
                mma_bf16(d0, ahi[0][ks], bl);
                mma_bf16(d0, alo[0][ks], bh);
                mma_bf16(d1, ahi[1][ks], bh);
                mma_bf16(d1, ahi[1][ks], bl);
                mma_bf16(d1, alo[1][ks], bh);
            }
            const int nb = 32 * ng + 8 * nt + 2 * l3;
            if (s <= 1) {
                const u32 hB = (s == 0) ? QH_B : KH_B;
                const u32 lB = (s == 0) ? QL_B : KL_B;
                #pragma unroll
                for (int q = 0; q < 4; ++q) {
                    int r = m0 + 16 * (q >> 1) + 8 * (q & 1);
                    float va = (q >> 1) ? d1[2 * (q & 1)]     : d0[2 * (q & 1)];
                    float vb = (q >> 1) ? d1[2 * (q & 1) + 1] : d0[2 * (q & 1) + 1];
                    u32 hp = cvt_bf2(va, vb);
                    u32 lp = cvt_bf2(va - __uint_as_float(hp << 16),
                                     vb - __uint_as_float(hp & 0xffff0000u));
                    *(u32*)(smc + hB + (u32)r * QK_STRIDE + nb * 2) = hp;
                    *(u32*)(smc + lB + (u32)r * QK_STRIDE + nb * 2) = lp;
                }
            } else if (s == 2) {
                #pragma unroll
                for (int q = 0; q < 4; ++q) {
                    int r = m0 + 16 * (q >> 1) + 8 * (q & 1);
                    if (r < 100) {
                        int bt = (r >= 50), f = r - 50 * bt;
                        float2 v;
                        v.x = (q >> 1) ? d1[2 * (q & 1)]     : d0[2 * (q & 1)];
                        v.y = (q >> 1) ? d1[2 * (q & 1) + 1] : d0[2 * (q & 1) + 1];
                        *(float2*)(out + (size_t)(2 * bid + bt) * (FF * CC) + f * CC + nb) = v;
                    }
                }
            } else {
                #pragma unroll
                for (int j = 0; j < 4; ++j) { dVreg[nt][j] = d0[j]; dVreg[nt][4 + j] = d1[j]; }
            }
        }

        __syncthreads();            // all reads of buf[s&1] done
        if (s < 2) {                // prefetch stage s+2 into the buffer just freed
            issue_w(g_Wimg[WIMG[s + 2]], smb, BUFB[s + 2], tid);
            CP_COMMIT();
        }
    }
    // last __syncthreads above: V stage reads of buf1 done -> region0 becomes Vt

    // ---- 4. drain V^T bf16 hi|lo into Vt[bt][n][g]; zero pad g in [50,64)
    {
        #pragma unroll
        for (int nt = 0; nt < 4; ++nt) {
            #pragma unroll
            for (int q = 0; q < 4; ++q) {
                int r = m0 + 16 * (q >> 1) + 8 * (q & 1);
                if (r < 100) {
                    int bt = (r >= 50), g = r - 50 * bt;
                    int n0 = 32 * ng + 8 * nt + 2 * l3;
                    float va = dVreg[nt][4 * (q >> 1) + 2 * (q & 1)];
                    float vb = dVreg[nt][4 * (q >> 1) + 2 * (q & 1) + 1];
                    u16 ha = __bfloat16_as_ushort(__float2bfloat16(va));
                    u16 hb = __bfloat16_as_ushort(__float2bfloat16(vb));
                    u16 la = __bfloat16_as_ushort(__float2bfloat16(va - __uint_as_float((u32)ha << 16)));
                    u16 lb = __bfloat16_as_ushort(__float2bfloat16(vb - __uint_as_float((u32)hb << 16)));
                    u32 base = (u32)bt * VT_BT + (u32)g * 2;
                    *(u16*)(smc + VTH_B + base + (u32)n0 * VT_STRIDE)       = ha;
                    *(u16*)(smc + VTH_B + base + (u32)(n0 + 1) * VT_STRIDE) = hb;
                    *(u16*)(smc + VTL_B + base + (u32)n0 * VT_STRIDE)       = la;
                    *(u16*)(smc + VTL_B + base + (u32)(n0 + 1) * VT_STRIDE) = lb;
                }
            }
        }
        // zero pad columns g in [50,64): 7 u32 per (bt,n) per image
        for (int i = tid; i < 2 * 128 * 7; i += 512) {
            int bt = i / 896, rem = i % 896;
            int n = rem / 7, j = rem % 7;
            u32 a = (u32)bt * VT_BT + (u32)n * VT_STRIDE + 100 + 4 * j;
            *(u32*)(smc + VTH_B + a) = 0;
            *(u32*)(smc + VTL_B + a) = 0;
        }
    }

    // ---- 5. scores: task (bt,h) = wid>>1; warp rows 32*sub (local), N=64, K=32
    const int task = wid >> 1;
    const int sub  = wid & 1;
    const int sbt  = task >> 2;
    const int sh   = task & 3;

    float dS[2][8][4];
    #pragma unroll
    for (int mt = 0; mt < 2; ++mt)
        #pragma unroll
        for (int nt = 0; nt < 8; ++nt)
            #pragma unroll
            for (int j = 0; j < 4; ++j) dS[mt][nt][j] = 0.f;

    {
        const u32 qr = (u32)(50 * sbt + 32 * sub);
        const int ii = lane >> 3;
        #pragma unroll
        for (int kb = 0; kb < 2; ++kb) {
            u32 aH[2][4], aL[2][4];
            #pragma unroll
            for (int mt = 0; mt < 2; ++mt) {
                u32 ad = smb + QH_B + (qr + 16 * mt + (lane & 15)) * QK_STRIDE
                       + 64 * sh + kb * 32 + 16 * (lane >> 4);
                ldsm4(aH[mt], ad);
                ldsm4(aL[mt], ad + (QL_B - QH_B));
            }
            #pragma unroll
            for (int p = 0; p < 4; ++p) {          // low-pressure B loads
                u32 bh4[4], bl4[4];
                u32 kd = smb + KH_B
                       + (u32)(50 * sbt + 8 * (2 * p + (ii >> 1)) + (lane & 7)) * QK_STRIDE
                       + 64 * sh + kb * 32 + 16 * (ii & 1);
                ldsm4(bh4, kd);
                ldsm4(bl4, kd + (KL_B - KH_B));
                #pragma unroll
                for (int mt = 0; mt < 2; ++mt)
                    #pragma unroll
                    for (int ntl = 0; ntl < 2; ++ntl) {
                        float* d = dS[mt][2 * p + ntl];
                        mma_bf16(d, aH[mt], &bh4[2 * ntl]);
                        mma_bf16(d, aL[mt], &bh4[2 * ntl]);
                        mma_bf16(d, aH[mt], &bl4[2 * ntl]);
                    }
            }
        }
    }

    // ---- 6. softmax in fragments
    #pragma unroll
    for (int mt = 0; mt < 2; ++mt)
        #pragma unroll
        for (int qq = 0; qq < 2; ++qq) {
            float mx = -3.4e38f;
            #pragma unroll
            for (int nt = 0; nt < 8; ++nt)
                #pragma unroll
                for (int c = 0; c < 2; ++c) {
                    bool ok = (nt < 6) || (nt == 6 && l3 == 0);   // col < 50
                    if (ok) mx = fmaxf(mx, dS[mt][nt][2 * qq + c]);
                }
            mx = fmaxf(mx, __shfl_xor_sync(0xffffffffu, mx, 1));
            mx = fmaxf(mx, __shfl_xor_sync(0xffffffffu, mx, 2));
            float su = 0.f;
            #pragma unroll
            for (int nt = 0; nt < 8; ++nt)
                #pragma unroll
                for (int c = 0; c < 2; ++c) {
                    bool ok = (nt < 6) || (nt == 6 && l3 == 0);
                    float e = ok ? __expf(dS[mt][nt][2 * qq + c] - mx) : 0.f;
                    dS[mt][nt][2 * qq + c] = e;
                    su += e;
                }
            su += __shfl_xor_sync(0xffffffffu, su, 1);
            su += __shfl_xor_sync(0xffffffffu, su, 2);
            float inv = 1.0f / su;
            #pragma unroll
            for (int nt = 0; nt < 8; ++nt) {
                dS[mt][nt][2 * qq]     *= inv;
                dS[mt][nt][2 * qq + 1] *= inv;
            }
        }

    __syncthreads();   // Vt fully written/zero-padded before AV reads

    // ---- 7+8. AV with lazy in-loop repack: M=32, N=32, K=64, 3 chains
    float dV[2][4][4];
    #pragma unroll
    for (int mt = 0; mt < 2; ++mt)
        #pragma unroll
        for (int nt = 0; nt < 4; ++nt)
            #pragma unroll
            for (int j = 0; j < 4; ++j) dV[mt][nt][j] = 0.f;
    {
        const int ii = lane >> 3;
        #pragma unroll
        for (int kb2 = 0; kb2 < 4; ++kb2) {
            // repack this k-block's attn D-frags -> bf16 hi|lo A-frags
            u32 pH[2][4], pL[2][4];
            #pragma unroll
            for (int mt = 0; mt < 2; ++mt)
                #pragma unroll
                for (int j = 0; j < 4; ++j) {
                    int nt = 2 * kb2 + (j >> 1);
                    float x0 = dS[mt][nt][2 * (j & 1)];
                    float x1 = dS[mt][nt][2 * (j & 1) + 1];
                    u32 hp = cvt_bf2(x0, x1);
                    pH[mt][j] = hp;
                    pL[mt][j] = cvt_bf2(x0 - __uint_as_float(hp << 16),
                                        x1 - __uint_as_float(hp & 0xffff0000u));
                }
            #pragma unroll
            for (int p = 0; p < 2; ++p) {
                u32 bh4[4], bl4[4];
                u32 vd = smb + VTH_B + (u32)sbt * VT_BT
                       + (u32)(32 * sh + 8 * (2 * p + (ii >> 1)) + (lane & 7)) * VT_STRIDE
                       + kb2 * 32 + 16 * (ii & 1);
                ldsm4(bh4, vd);
                ldsm4(bl4, vd + (VTL_B - VTH_B));
                #pragma unroll
                for (int mt = 0; mt < 2; ++mt)
                    #pragma unroll
                    for (int ntl = 0; ntl < 2; ++ntl) {
                        float* d = dV[mt][2 * p + ntl];
                        mma_bf16(d, pH[mt], &bh4[2 * ntl]);
                        mma_bf16(d, pL[mt], &bh4[2 * ntl]);
                        mma_bf16(d, pH[mt], &bl4[2 * ntl]);
                    }
            }
        }
    }

    // ---- 9. epilogue: out = relu(AV + R)  (R pre-stored in out by stage 2)
    {
        float* outB = out + (size_t)(2 * bid + sbt) * (FF * CC);
        #pragma unroll
        for (int mt = 0; mt < 2; ++mt)
            #pragma unroll
            for (int qq = 0; qq < 2; ++qq) {
                int fl = 32 * sub + 16 * mt + 8 * qq + (lane >> 2);
                if (fl < 50) {
                    #pragma unroll
                    for (int nt = 0; nt < 4; ++nt) {
                        int col = 32 * sh + 8 * nt + 2 * l3;
                        float2* p = (float2*)(outB + fl * CC + col);
                        float2 rv = *p;
                        float2 o;
                        o.x = fmaxf(dV[mt][nt][2 * qq]     + rv.x, 0.f);
                        o.y = fmaxf(dV[mt][nt][2 * qq + 1] + rv.y, 0.f);
                        *p = o;
                    }
                }
            }
    }
}

extern "C" void kernel_launch(void* const* d_in, const int* in_sizes, int n_in,
                              void* d_out, int out_size)
{
    const float* X  = (const float*)d_in[0];
    const float* Wq = (const float*)d_in[1];
    const float* Wk = (const float*)d_in[2];
    const float* Wv = (const float*)d_in[3];
    const float* Wr = (const float*)d_in[4];
    float* out = (float*)d_out;

    prep_w<<<64, 512>>>(Wq, Wk, Wv, Wr);
    cudaFuncSetAttribute(autoint_v7,
                         cudaFuncAttributeMaxDynamicSharedMemorySize, SMEM_BYTES);
    autoint_v7<<<BB / 2, 512, SMEM_BYTES>>>(X, out);
}